// round 1
// baseline (speedup 1.0000x reference)
#include <cuda_runtime.h>
#include <cstdint>

#define N_NODES 8192
#define H 64
#define F 10
#define NN ((size_t)N_NODES * (size_t)N_NODES)

// Scratch (no allocs allowed): h and aggregation buffers, 2 MB each.
__device__ float g_h[N_NODES * H];
__device__ float g_agg[N_NODES * H];

// ---------------- packed f32x2 helpers (sm_100+ FFMA2 path) ----------------
__device__ __forceinline__ unsigned long long pack2(float lo, float hi) {
    unsigned long long r;
    asm("mov.b64 %0, {%1, %2};" : "=l"(r)
        : "r"(__float_as_uint(lo)), "r"(__float_as_uint(hi)));
    return r;
}
__device__ __forceinline__ void fma2(unsigned long long& d,
                                     unsigned long long a,
                                     unsigned long long b) {
    asm("fma.rn.f32x2 %0, %1, %2, %0;" : "+l"(d) : "l"(a), "l"(b));
}
union F2U { unsigned long long u; float2 f; };

// ---------------- kernel 1: h0 = relu(features @ W_node + b_node) ----------
__global__ void k_mlp(const float* __restrict__ feat,
                      const float* __restrict__ W,
                      const float* __restrict__ b) {
    __shared__ float fs[F];
    int n = blockIdx.x;
    int j = threadIdx.x;
    if (j < F) fs[j] = feat[n * F + j];
    __syncthreads();
    float acc = b[j];
#pragma unroll
    for (int k = 0; k < F; k++) acc = fmaf(fs[k], W[k * H + j], acc);
    g_h[n * H + j] = fmaxf(acc, 0.f);
}

// ---------------- zero agg ----------------
__global__ void k_zero() {
    int t = blockIdx.x * blockDim.x + threadIdx.x;
    ((float4*)g_agg)[t] = make_float4(0.f, 0.f, 0.f, 0.f);
}

// ---------------- scatter: agg[dst] += h[src] (vector fp32 reduction) ------
__global__ void k_scatter(const int* __restrict__ edges, int E) {
    int t = blockIdx.x * blockDim.x + threadIdx.x;
    int e = t >> 4;
    if (e >= E) return;
    int p = (t & 15) * 4;
    int src = edges[2 * e];
    int dst = edges[2 * e + 1];
    float4 v = *(const float4*)&g_h[src * H + p];
    float* d = &g_agg[dst * H + p];
    asm volatile("red.global.add.v4.f32 [%0], {%1,%2,%3,%4};"
                 :: "l"(d), "f"(v.x), "f"(v.y), "f"(v.z), "f"(v.w)
                 : "memory");
}

// ---------------- conv update: h = relu((h+agg) @ W_conv + b_conv) ---------
__global__ void k_conv(const float* __restrict__ Wc,
                       const float* __restrict__ bc) {
    __shared__ float Ws[H * H];
    __shared__ float rows[4][H];
    int t = threadIdx.x;
#pragma unroll
    for (int i = 0; i < 16; i++) Ws[t + i * 256] = Wc[t + i * 256];
    int rloc = t >> 6;
    int j = t & 63;
    int r = blockIdx.x * 4 + rloc;
    rows[rloc][j] = g_h[r * H + j] + g_agg[r * H + j];
    __syncthreads();
    float acc = bc[j];
    const float* row = rows[rloc];
#pragma unroll
    for (int k = 0; k < H; k++) acc = fmaf(row[k], Ws[k * H + j], acc);
    g_h[r * H + j] = fmaxf(acc, 0.f);
}

// ---------------- fused output GEMM: sim = h@h^T, fd = mask*sim*mask -------
// 128x128 tile / block, 256 threads, 8x8 per thread, K=64 resident in smem.
// f32x2 packed FMA accumulators (pairs along i).
#define ASTR 132   // smem row stride (floats): 132 % 32 == 4 -> conflict-free fill
__global__ __launch_bounds__(256, 2) void k_gemm(const int* __restrict__ nodes,
                                                 float* __restrict__ out) {
    extern __shared__ float smem[];
    float* As = smem;                 // [64][ASTR] k-major A tile
    float* Bs = smem + 64 * ASTR;     // [64][ASTR] k-major B tile
    __shared__ float mA[128], mB[128];

    int bi = blockIdx.y, bj = blockIdx.x;
    int t = threadIdx.x;
    int tx = t & 15, ty = t >> 4;

    if (t < 128) mA[t] = (nodes[bi * 128 + t] == 2) ? 1.f : 0.f;
    else         mB[t - 128] = (nodes[bj * 128 + (t - 128)] == 2) ? 1.f : 0.f;

    // Load both 128x64 tiles of h, transposing to k-major smem.
    {
        int r = t >> 1, hq = t & 1;
        const float* Ag = g_h + (size_t)bi * 128 * H;
        const float* Bg = g_h + (size_t)bj * 128 * H;
#pragma unroll
        for (int q = 0; q < 8; q++) {
            int k4 = q * 2 + hq;
            float4 va = *(const float4*)&Ag[r * H + k4 * 4];
            float4 vb = *(const float4*)&Bg[r * H + k4 * 4];
            int k = k4 * 4;
            As[(k + 0) * ASTR + r] = va.x; As[(k + 1) * ASTR + r] = va.y;
            As[(k + 2) * ASTR + r] = va.z; As[(k + 3) * ASTR + r] = va.w;
            Bs[(k + 0) * ASTR + r] = vb.x; Bs[(k + 1) * ASTR + r] = vb.y;
            Bs[(k + 2) * ASTR + r] = vb.z; Bs[(k + 3) * ASTR + r] = vb.w;
        }
    }
    __syncthreads();

    // acc[p][q]: i-pair p (pairs within i-quads ty*4.. and 64+ty*4..), j index q
    unsigned long long acc[4][8];
#pragma unroll
    for (int p = 0; p < 4; p++)
#pragma unroll
        for (int q = 0; q < 8; q++) acc[p][q] = 0ull;

    for (int k0 = 0; k0 < 64; k0 += 8) {
#pragma unroll
        for (int kk = 0; kk < 8; kk++) {
            int k = k0 + kk;
            const float* ak = &As[k * ASTR];
            const float* bk = &Bs[k * ASTR];
            float4 a0 = *(const float4*)&ak[ty * 4];
            float4 a1 = *(const float4*)&ak[64 + ty * 4];
            float4 b0 = *(const float4*)&bk[tx * 4];
            float4 b1 = *(const float4*)&bk[64 + tx * 4];
            unsigned long long pa[4], pb[8];
            pa[0] = pack2(a0.x, a0.y); pa[1] = pack2(a0.z, a0.w);
            pa[2] = pack2(a1.x, a1.y); pa[3] = pack2(a1.z, a1.w);
            pb[0] = pack2(b0.x, b0.x); pb[1] = pack2(b0.y, b0.y);
            pb[2] = pack2(b0.z, b0.z); pb[3] = pack2(b0.w, b0.w);
            pb[4] = pack2(b1.x, b1.x); pb[5] = pack2(b1.y, b1.y);
            pb[6] = pack2(b1.z, b1.z); pb[7] = pack2(b1.w, b1.w);
#pragma unroll
            for (int p = 0; p < 4; p++)
#pragma unroll
                for (int q = 0; q < 8; q++) fma2(acc[p][q], pa[p], pb[q]);
        }
    }

    // Write both outputs: out[0..NN) = function_deps, out[NN..2NN) = similarity
    float* fd  = out;
    float* sim = out + NN;
    float4 mb0 = *(const float4*)&mB[tx * 4];
    float4 mb1 = *(const float4*)&mB[64 + tx * 4];

#pragma unroll
    for (int p = 0; p < 4; p++) {
        float2 u[8];
#pragma unroll
        for (int q = 0; q < 8; q++) { F2U cv; cv.u = acc[p][q]; u[q] = cv.f; }
#pragma unroll
        for (int e = 0; e < 2; e++) {
            int ii = 2 * p + e;
            int il = (ii < 4) ? (ty * 4 + ii) : (64 + ty * 4 + (ii - 4));
            size_t ro = (size_t)(bi * 128 + il) * N_NODES + (size_t)bj * 128;
            float4 s0, s1;
            if (e == 0) {
                s0 = make_float4(u[0].x, u[1].x, u[2].x, u[3].x);
                s1 = make_float4(u[4].x, u[5].x, u[6].x, u[7].x);
            } else {
                s0 = make_float4(u[0].y, u[1].y, u[2].y, u[3].y);
                s1 = make_float4(u[4].y, u[5].y, u[6].y, u[7].y);
            }
            *(float4*)&sim[ro + tx * 4]      = s0;
            *(float4*)&sim[ro + 64 + tx * 4] = s1;
            float ma = mA[il];
            float4 f0 = make_float4(s0.x * ma * mb0.x, s0.y * ma * mb0.y,
                                    s0.z * ma * mb0.z, s0.w * ma * mb0.w);
            float4 f1 = make_float4(s1.x * ma * mb1.x, s1.y * ma * mb1.y,
                                    s1.z * ma * mb1.z, s1.w * ma * mb1.w);
            *(float4*)&fd[ro + tx * 4]      = f0;
            *(float4*)&fd[ro + 64 + tx * 4] = f1;
        }
    }
}

extern "C" void kernel_launch(void* const* d_in, const int* in_sizes, int n_in,
                              void* d_out, int out_size) {
    const float* feat  = (const float*)d_in[0];
    const float* Wn    = (const float*)d_in[1];
    const float* bn    = (const float*)d_in[2];
    const float* Wc    = (const float*)d_in[3];
    const float* bc    = (const float*)d_in[4];
    const int*   nodes = (const int*)d_in[5];
    const int*   edges = (const int*)d_in[6];
    int E = in_sizes[6] / 2;

    k_mlp<<<N_NODES, 64>>>(feat, Wn, bn);
    for (int r = 0; r < 2; r++) {
        k_zero<<<(N_NODES * H / 4) / 256, 256>>>();
        k_scatter<<<(E * 16 + 255) / 256, 256>>>(edges, E);
        k_conv<<<N_NODES / 4, 256>>>(Wc, bc);
    }

    cudaFuncSetAttribute(k_gemm, cudaFuncAttributeMaxDynamicSharedMemorySize,
                         2 * 64 * ASTR * (int)sizeof(float));
    k_gemm<<<dim3(N_NODES / 128, N_NODES / 128), 256,
             2 * 64 * ASTR * (int)sizeof(float)>>>(nodes, (float*)d_out);
}

// round 3
// speedup vs baseline: 1.1742x; 1.1742x over previous
#include <cuda_runtime.h>
#include <cstdint>

#define N_NODES 8192
#define H 64
#define F 10
#define NN ((size_t)N_NODES * (size_t)N_NODES)

// Scratch (no allocs allowed): h and aggregation buffers, 2 MB each.
__device__ float g_h[N_NODES * H];
__device__ float g_agg[N_NODES * H];

// ---------------- packed f32x2 helpers (sm_100+ FFMA2 path) ----------------
__device__ __forceinline__ unsigned long long pack2(float lo, float hi) {
    unsigned long long r;
    asm("mov.b64 %0, {%1, %2};" : "=l"(r)
        : "r"(__float_as_uint(lo)), "r"(__float_as_uint(hi)));
    return r;
}
__device__ __forceinline__ void fma2(unsigned long long& d,
                                     unsigned long long a,
                                     unsigned long long b) {
    asm("fma.rn.f32x2 %0, %1, %2, %0;" : "+l"(d) : "l"(a), "l"(b));
}
union F2U { unsigned long long u; float2 f; };

// ---------------- kernel 1: h0 = relu(features @ W_node + b_node) ----------
__global__ void k_mlp(const float* __restrict__ feat,
                      const float* __restrict__ W,
                      const float* __restrict__ b) {
    __shared__ float fs[F];
    int n = blockIdx.x;
    int j = threadIdx.x;
    if (j < F) fs[j] = feat[n * F + j];
    __syncthreads();
    float acc = b[j];
#pragma unroll
    for (int k = 0; k < F; k++) acc = fmaf(fs[k], W[k * H + j], acc);
    g_h[n * H + j] = fmaxf(acc, 0.f);
}

// ---------------- zero agg ----------------
__global__ void k_zero() {
    int t = blockIdx.x * blockDim.x + threadIdx.x;
    ((float4*)g_agg)[t] = make_float4(0.f, 0.f, 0.f, 0.f);
}

// ---------------- scatter: agg[dst] += h[src] (vector fp32 reduction) ------
__global__ void k_scatter(const int* __restrict__ edges, int E) {
    int t = blockIdx.x * blockDim.x + threadIdx.x;
    int e = t >> 4;
    if (e >= E) return;
    int p = (t & 15) * 4;
    int src = edges[2 * e];
    int dst = edges[2 * e + 1];
    float4 v = *(const float4*)&g_h[src * H + p];
    float* d = &g_agg[dst * H + p];
    asm volatile("red.global.add.v4.f32 [%0], {%1,%2,%3,%4};"
                 :: "l"(d), "f"(v.x), "f"(v.y), "f"(v.z), "f"(v.w)
                 : "memory");
}

// ---------------- conv update: h = relu((h+agg) @ W_conv + b_conv) ---------
// 16 rows per block: amortize the 16KB W tile over 4 outputs/thread.
__global__ void k_conv(const float* __restrict__ Wc,
                       const float* __restrict__ bc) {
    __shared__ float Ws[H * H];
    __shared__ float rows[16][H];
    int t = threadIdx.x;
#pragma unroll
    for (int i = 0; i < 16; i++) Ws[t + i * 256] = Wc[t + i * 256];
    int j = t & 63;
    int rbase = blockIdx.x * 16;
    {
        float4 hv = ((const float4*)(g_h + (size_t)rbase * H))[t];
        float4 av = ((const float4*)(g_agg + (size_t)rbase * H))[t];
        ((float4*)&rows[0][0])[t] =
            make_float4(hv.x + av.x, hv.y + av.y, hv.z + av.z, hv.w + av.w);
    }
    __syncthreads();
    int r0 = t >> 6;  // 0..3
    float bias = bc[j];
    float a0 = bias, a1 = bias, a2 = bias, a3 = bias;
#pragma unroll
    for (int k = 0; k < H; k++) {
        float w = Ws[k * H + j];
        a0 = fmaf(rows[r0][k], w, a0);
        a1 = fmaf(rows[r0 + 4][k], w, a1);
        a2 = fmaf(rows[r0 + 8][k], w, a2);
        a3 = fmaf(rows[r0 + 12][k], w, a3);
    }
    g_h[(size_t)(rbase + r0) * H + j]      = fmaxf(a0, 0.f);
    g_h[(size_t)(rbase + r0 + 4) * H + j]  = fmaxf(a1, 0.f);
    g_h[(size_t)(rbase + r0 + 8) * H + j]  = fmaxf(a2, 0.f);
    g_h[(size_t)(rbase + r0 + 12) * H + j] = fmaxf(a3, 0.f);
}

// ---------------- fused output GEMM: sim = h@h^T, fd = mask*sim*mask -------
// Symmetric: only upper-triangle tiles (bj >= bi) computed; off-diagonal
// tiles are written twice (normal + mirrored via register il-quads).
// 128x128 tile / block, 256 threads, 8x8 per thread, K=64 resident in smem.
#define ASTR 132   // smem row stride (floats): conflict-free k-major fill
__global__ __launch_bounds__(256, 2) void k_gemm(const int* __restrict__ nodes,
                                                 float* __restrict__ out) {
    int bi = blockIdx.y, bj = blockIdx.x;
    if (bj < bi) return;  // symmetry: upper triangle only

    extern __shared__ float smem[];
    float* As = smem;                 // [64][ASTR] k-major A tile
    float* Bs = smem + 64 * ASTR;     // [64][ASTR] k-major B tile
    __shared__ float mA[128], mB[128];

    int t = threadIdx.x;
    int tx = t & 15, ty = t >> 4;

    if (t < 128) mA[t] = (nodes[bi * 128 + t] == 2) ? 1.f : 0.f;
    else         mB[t - 128] = (nodes[bj * 128 + (t - 128)] == 2) ? 1.f : 0.f;

    // Load both 128x64 tiles of h, transposing to k-major smem.
    {
        int r = t >> 1, hq = t & 1;
        const float* Ag = g_h + (size_t)bi * 128 * H;
        const float* Bg = g_h + (size_t)bj * 128 * H;
#pragma unroll
        for (int q = 0; q < 8; q++) {
            int k4 = q * 2 + hq;
            float4 va = *(const float4*)&Ag[r * H + k4 * 4];
            float4 vb = *(const float4*)&Bg[r * H + k4 * 4];
            int k = k4 * 4;
            As[(k + 0) * ASTR + r] = va.x; As[(k + 1) * ASTR + r] = va.y;
            As[(k + 2) * ASTR + r] = va.z; As[(k + 3) * ASTR + r] = va.w;
            Bs[(k + 0) * ASTR + r] = vb.x; Bs[(k + 1) * ASTR + r] = vb.y;
            Bs[(k + 2) * ASTR + r] = vb.z; Bs[(k + 3) * ASTR + r] = vb.w;
        }
    }
    __syncthreads();

    // acc[p][q]: i-pair p, j index q. il(p,e): p<2 -> ty*4+2p+e ; p>=2 -> 64+ty*4+2(p-2)+e
    unsigned long long acc[4][8];
#pragma unroll
    for (int p = 0; p < 4; p++)
#pragma unroll
        for (int q = 0; q < 8; q++) acc[p][q] = 0ull;

    for (int k0 = 0; k0 < 64; k0 += 8) {
#pragma unroll
        for (int kk = 0; kk < 8; kk++) {
            int k = k0 + kk;
            const float* ak = &As[k * ASTR];
            const float* bk = &Bs[k * ASTR];
            float4 a0 = *(const float4*)&ak[ty * 4];
            float4 a1 = *(const float4*)&ak[64 + ty * 4];
            float4 b0 = *(const float4*)&bk[tx * 4];
            float4 b1 = *(const float4*)&bk[64 + tx * 4];
            unsigned long long pa[4], pb[8];
            pa[0] = pack2(a0.x, a0.y); pa[1] = pack2(a0.z, a0.w);
            pa[2] = pack2(a1.x, a1.y); pa[3] = pack2(a1.z, a1.w);
            pb[0] = pack2(b0.x, b0.x); pb[1] = pack2(b0.y, b0.y);
            pb[2] = pack2(b0.z, b0.z); pb[3] = pack2(b0.w, b0.w);
            pb[4] = pack2(b1.x, b1.x); pb[5] = pack2(b1.y, b1.y);
            pb[6] = pack2(b1.z, b1.z); pb[7] = pack2(b1.w, b1.w);
#pragma unroll
            for (int p = 0; p < 4; p++)
#pragma unroll
                for (int q = 0; q < 8; q++) fma2(acc[p][q], pa[p], pb[q]);
        }
    }

    // Unpack all accumulators once.
    float2 u[4][8];
#pragma unroll
    for (int p = 0; p < 4; p++)
#pragma unroll
        for (int q = 0; q < 8; q++) { F2U cv; cv.u = acc[p][q]; u[p][q] = cv.f; }

    float* fd  = out;
    float* sim = out + NN;
    float4 mb0 = *(const float4*)&mB[tx * 4];
    float4 mb1 = *(const float4*)&mB[64 + tx * 4];
    float4 ma0 = *(const float4*)&mA[ty * 4];
    float4 ma1 = *(const float4*)&mA[64 + ty * 4];

    // ---- normal tile writes (rows = il, coalesced along jl) ----
#pragma unroll
    for (int p = 0; p < 4; p++) {
#pragma unroll
        for (int e = 0; e < 2; e++) {
            int ii = 2 * p + e;
            int il = (ii < 4) ? (ty * 4 + ii) : (64 + ty * 4 + (ii - 4));
            size_t ro = (size_t)(bi * 128 + il) * N_NODES + (size_t)bj * 128;
            float4 s0, s1;
            if (e == 0) {
                s0 = make_float4(u[p][0].x, u[p][1].x, u[p][2].x, u[p][3].x);
                s1 = make_float4(u[p][4].x, u[p][5].x, u[p][6].x, u[p][7].x);
            } else {
                s0 = make_float4(u[p][0].y, u[p][1].y, u[p][2].y, u[p][3].y);
                s1 = make_float4(u[p][4].y, u[p][5].y, u[p][6].y, u[p][7].y);
            }
            *(float4*)&sim[ro + tx * 4]      = s0;
            *(float4*)&sim[ro + 64 + tx * 4] = s1;
            float ma = (ii < 4) ? ((const float*)&ma0)[ii] : ((const float*)&ma1)[ii - 4];
            float4 f0 = make_float4(s0.x * ma * mb0.x, s0.y * ma * mb0.y,
                                    s0.z * ma * mb0.z, s0.w * ma * mb0.w);
            float4 f1 = make_float4(s1.x * ma * mb1.x, s1.y * ma * mb1.y,
                                    s1.z * ma * mb1.z, s1.w * ma * mb1.w);
            *(float4*)&fd[ro + tx * 4]      = f0;
            *(float4*)&fd[ro + 64 + tx * 4] = f1;
        }
    }

    // ---- mirror tile writes (rows = jl, float4 along il) ----
    if (bi != bj) {
#pragma unroll
        for (int q = 0; q < 8; q++) {
            int jl = (q < 4) ? (tx * 4 + q) : (64 + tx * 4 + (q - 4));
            size_t ro = (size_t)(bj * 128 + jl) * N_NODES + (size_t)bi * 128;
            float4 s0 = make_float4(u[0][q].x, u[0][q].y, u[1][q].x, u[1][q].y);
            float4 s1 = make_float4(u[2][q].x, u[2][q].y, u[3][q].x, u[3][q].y);
            *(float4*)&sim[ro + ty * 4]      = s0;
            *(float4*)&sim[ro + 64 + ty * 4] = s1;
            float mb = (q < 4) ? ((const float*)&mb0)[q] : ((const float*)&mb1)[q - 4];
            float4 f0 = make_float4(s0.x * mb * ma0.x, s0.y * mb * ma0.y,
                                    s0.z * mb * ma0.z, s0.w * mb * ma0.w);
            float4 f1 = make_float4(s1.x * mb * ma1.x, s1.y * mb * ma1.y,
                                    s1.z * mb * ma1.z, s1.w * mb * ma1.w);
            *(float4*)&fd[ro + ty * 4]      = f0;
            *(float4*)&fd[ro + 64 + ty * 4] = f1;
        }
    }
}

extern "C" void kernel_launch(void* const* d_in, const int* in_sizes, int n_in,
                              void* d_out, int out_size) {
    const float* feat  = (const float*)d_in[0];
    const float* Wn    = (const float*)d_in[1];
    const float* bn    = (const float*)d_in[2];
    const float* Wc    = (const float*)d_in[3];
    const float* bc    = (const float*)d_in[4];
    const int*   nodes = (const int*)d_in[5];
    const int*   edges = (const int*)d_in[6];
    int E = in_sizes[6] / 2;

    k_mlp<<<N_NODES, 64>>>(feat, Wn, bn);
    for (int r = 0; r < 2; r++) {
        k_zero<<<(N_NODES * H / 4) / 256, 256>>>();
        k_scatter<<<(E * 16 + 255) / 256, 256>>>(edges, E);
        k_conv<<<N_NODES / 16, 256>>>(Wc, bc);
    }

    cudaFuncSetAttribute(k_gemm, cudaFuncAttributeMaxDynamicSharedMemorySize,
                         2 * 64 * ASTR * (int)sizeof(float));
    k_gemm<<<dim3(N_NODES / 128, N_NODES / 128), 256,
             2 * 64 * ASTR * (int)sizeof(float)>>>(nodes, (float*)d_out);
}